// round 6
// baseline (speedup 1.0000x reference)
#include <cuda_runtime.h>
#include <cuda_fp16.h>
#include <cstdint>

#define BB 8
#define CC 256
#define HH 64
#define WW 64
#define OO 256
#define KK2 9
#define PLANE 4096
#define NROWS 4
#define NPIX 256          // N per CTA
#define NCH 144           // chunks: 16 c-groups (outer) x 9 taps (inner)
#define APITCH 48
#define BPITCH 48
#define A_BUF_BYTES (128 * APITCH)   // 6144
#define B_BUF_BYTES (256 * BPITCH)   // 12288

// plane window
#define WIN_LO 6
#define WIN_ROWS 16
#define XPAD 2
#define XW 68                         // x0i in [0,66], elements [0,67]
#define PP_PER_CP (WIN_ROWS * XW)     // 1088 uint2 per channel-pair
#define PP_ELEMS (8 * PP_PER_CP)      // 8704 uint2 = 69632 B

// smem layout (dynamic)
#define SM_TAPS 0                     // float2[9*256] = 18432
#define SM_PP   18432                 // 69632 -> 88064
#define SM_A    88064                 // 2 * 6144  -> 100352
#define SM_B    100352                // 2 * 12288 -> 124928
#define SMEM_TOTAL 124928

__device__ __forceinline__ uint32_t smem_u32(const void* p) {
    uint32_t a;
    asm("{ .reg .u64 t; cvta.to.shared.u64 t, %1; cvt.u32.u64 %0, t; }"
        : "=r"(a) : "l"(p));
    return a;
}

__device__ __forceinline__ void ldmx4(uint32_t* r, uint32_t addr) {
    asm volatile("ldmatrix.sync.aligned.m8n8.x4.shared.b16 {%0,%1,%2,%3}, [%4];"
                 : "=r"(r[0]), "=r"(r[1]), "=r"(r[2]), "=r"(r[3]) : "r"(addr));
}

__device__ __forceinline__ void mma16816(float* d, const uint32_t* a,
                                         uint32_t b0, uint32_t b1) {
    asm volatile(
        "mma.sync.aligned.m16n8k16.row.col.f32.f16.f16.f32 "
        "{%0,%1,%2,%3}, {%4,%5,%6,%7}, {%8,%9}, {%0,%1,%2,%3};"
        : "+f"(d[0]), "+f"(d[1]), "+f"(d[2]), "+f"(d[3])
        : "r"(a[0]), "r"(a[1]), "r"(a[2]), "r"(a[3]), "r"(b0), "r"(b1));
}

// Pre-packed fp16 weights, chunk-major: g_wh[q][o][j], q = cg*9 + k, j = c-local
__device__ __half g_wh[NCH * OO * 16];   // 1.18 MB

__global__ void prep_w(const float* __restrict__ w) {
    int n = blockIdx.x * blockDim.x + threadIdx.x;   // over 144*256*16
    if (n >= NCH * OO * 16) return;
    int j = n & 15;
    int o = (n >> 4) & 255;
    int q = n >> 12;
    int cg = q / 9;
    int k  = q - cg * 9;
    int c  = cg * 16 + j;
    g_wh[n] = __float2half(w[(o * CC + c) * KK2 + k]);
}

__global__ __launch_bounds__(256, 1)
void dcn_kernel(const float* __restrict__ x,
                const float* __restrict__ offset,
                float* __restrict__ out) {
    extern __shared__ char smem[];
    float2* taps = (float2*)(smem + SM_TAPS);   // [k*256 + p] = (py, px)
    uint2*  spp  = (uint2*) (smem + SM_PP);

    const int tid = threadIdx.x;
    const int lid = tid & 31;
    const int wid = tid >> 5;
    const int wm  = wid >> 2;            // 0..1 : warp m (64 rows)
    const int wn  = wid & 3;             // 0..3 : warp n (64 px)
    const int b   = blockIdx.y;
    const int h0  = blockIdx.x * NROWS;
    const int mh  = blockIdx.z;          // o-half (0/1)

    // ---- precompute absolute sample coords per (k, pixel) ----
    for (int i = tid; i < KK2 * NPIX; i += 256) {
        int k = i >> 8;
        int p = i & 255;
        int rl = p >> 6, wc = p & 63;
        int h = h0 + rl;
        int ky = k / 3, kx = k - ky * 3;
        float dy = offset[(((b * 2 * KK2 + 2 * k    ) * HH + h) * WW) + wc];
        float dx = offset[(((b * 2 * KK2 + 2 * k + 1) * HH + h) * WW) + wc];
        taps[i] = make_float2((float)(h - 1 + ky) + dy, (float)(wc - 1 + kx) + dx);
    }

    const uint32_t smA = smem_u32(smem + SM_A);
    const uint32_t smB = smem_u32(smem + SM_B);

    // ldmatrix per-thread address offsets (within a buffer)
    const int r   = lid & 7;
    const int sec = lid >> 3;
    const uint32_t aoff = (uint32_t)(wm * 64 + r + 8 * (sec & 1)) * APITCH
                        + (uint32_t)(sec >> 1) * 16;
    const uint32_t boff = (uint32_t)(wn * 64 + r + 8 * (sec >> 1)) * BPITCH
                        + (uint32_t)(sec & 1) * 16;

    const float* xb = x + (size_t)b * CC * PLANE;
    const char*  wsrc = (const char*)g_wh + (size_t)mh * 4096;  // m-half offset
    const int arow = tid >> 1, ahalf = tid & 1;

    float acc[4][8][4];
#pragma unroll
    for (int i = 0; i < 4; i++)
#pragma unroll
        for (int j = 0; j < 8; j++)
#pragma unroll
            for (int t = 0; t < 4; t++) acc[i][j][t] = 0.f;

    uint32_t sbuf[8];
    uint4    areg;
    __syncthreads();   // taps visible

    // prologue: A prefetch for q=0
    areg = *(const uint4*)(wsrc + arow * 32 + ahalf * 16);

    for (int cg = 0; cg < 16; cg++) {
        // ---- stage 16 channels (8 pairs) x 16-row window, fp16 dup-pairs ----
        {
            const float* cbase = xb + (size_t)(cg * 16) * PLANE;
            for (int e = tid; e < PP_ELEMS; e += 256) {
                int cp  = e / PP_PER_CP;
                int rem = e - cp * PP_PER_CP;
                int row = rem / XW;
                int xi  = rem - row * XW;
                int y   = h0 - WIN_LO + row;
                int xx  = xi - XPAD;
                const float* p0 = cbase + (size_t)(cp * 2) * PLANE + y * WW;
                const float* p1 = p0 + PLANE;
                float v00 = 0.f, v01 = 0.f, v10 = 0.f, v11 = 0.f;
                if (y >= 0 && y < HH) {
                    if (xx >= 0 && xx < WW)         { v00 = __ldg(p0 + xx);     v10 = __ldg(p1 + xx); }
                    if (xx + 1 >= 0 && xx + 1 < WW) { v01 = __ldg(p0 + xx + 1); v11 = __ldg(p1 + xx + 1); }
                }
                __half2 ha = __floats2half2_rn(v00, v01);
                __half2 hb = __floats2half2_rn(v10, v11);
                uint2 val;
                val.x = *(uint32_t*)&ha;
                val.y = *(uint32_t*)&hb;
                spp[e] = val;
            }
        }
        __syncthreads();   // planes visible

#pragma unroll 1
        for (int k = 0; k < KK2; k++) {
            const int q = cg * 9 + k;
            const int buf = q & 1;

            // ---- sample 16 channels for my pixel at tap k ----
            {
                float2 t = taps[k * 256 + tid];
                float py = t.x, px = t.y;
                float y0f = floorf(py), x0f = floorf(px);
                float fy = py - y0f, fx = px - x0f;
                int rowi = (int)y0f - (h0 - WIN_LO);
                int x0i  = (int)x0f + XPAD;
                float w00 = (1.f - fy) * (1.f - fx);
                float w01 = (1.f - fy) * fx;
                float w10 = fy * (1.f - fx);
                float w11 = fy * fx;
                bool fb = (rowi < 0) | (rowi > WIN_ROWS - 2)
                        | (x0i < 0) | (x0i > XW - 2);
                if (!fb) {
                    const uint2* pt = spp + rowi * XW + x0i;
#pragma unroll
                    for (int cp = 0; cp < 8; cp++) {
                        uint2 top = pt[cp * PP_PER_CP];
                        uint2 bot = pt[cp * PP_PER_CP + XW];
                        float2 ta = __half22float2(*(__half2*)&top.x);
                        float2 tb = __half22float2(*(__half2*)&top.y);
                        float2 ba = __half22float2(*(__half2*)&bot.x);
                        float2 bb = __half22float2(*(__half2*)&bot.y);
                        float s0 = w00 * ta.x + w01 * ta.y + w10 * ba.x + w11 * ba.y;
                        float s1 = w00 * tb.x + w01 * tb.y + w10 * bb.x + w11 * bb.y;
                        __half2 hh = __floats2half2_rn(s0, s1);
                        sbuf[cp] = *(uint32_t*)&hh;
                    }
                } else {
                    // rare fallback: direct gmem bilinear gather (exact semantics)
                    int y0 = (int)y0f, x0 = (int)x0f;
                    int y1 = y0 + 1, x1 = x0 + 1;
                    bool vy0 = (y0 >= 0) && (y0 < HH);
                    bool vy1 = (y1 >= 0) && (y1 < HH);
                    bool vx0 = (x0 >= 0) && (x0 < WW);
                    bool vx1 = (x1 >= 0) && (x1 < WW);
                    float W00 = (vy0 && vx0) ? w00 : 0.f;
                    float W01 = (vy0 && vx1) ? w01 : 0.f;
                    float W10 = (vy1 && vx0) ? w10 : 0.f;
                    float W11 = (vy1 && vx1) ? w11 : 0.f;
                    int cy0 = min(max(y0, 0), HH - 1), cy1 = min(max(y1, 0), HH - 1);
                    int cx0 = min(max(x0, 0), WW - 1), cx1 = min(max(x1, 0), WW - 1);
                    int i00 = cy0 * WW + cx0, i01 = cy0 * WW + cx1;
                    int i10 = cy1 * WW + cx0, i11 = cy1 * WW + cx1;
                    const float* xp = xb + (size_t)(cg * 16) * PLANE;
                    float sv[16];
#pragma unroll
                    for (int j = 0; j < 16; j++) {
                        sv[j] = W00 * __ldg(xp + i00) + W01 * __ldg(xp + i01)
                              + W10 * __ldg(xp + i10) + W11 * __ldg(xp + i11);
                        xp += PLANE;
                    }
#pragma unroll
                    for (int cp = 0; cp < 8; cp++) {
                        __half2 hh = __floats2half2_rn(sv[2 * cp], sv[2 * cp + 1]);
                        sbuf[cp] = *(uint32_t*)&hh;
                    }
                }
            }

            // ---- stage A (prefetched) + B into smem buffers ----
            {
                char* ad = smem + SM_A + buf * A_BUF_BYTES + arow * APITCH + ahalf * 16;
                *(uint4*)ad = areg;
                char* bd = smem + SM_B + buf * B_BUF_BYTES + tid * BPITCH;
                *(uint4*)(bd)      = *(uint4*)&sbuf[0];
                *(uint4*)(bd + 16) = *(uint4*)&sbuf[4];
            }
            // prefetch A for q+1
            if (q + 1 < NCH)
                areg = *(const uint4*)(wsrc + (size_t)(q + 1) * 8192
                                       + arow * 32 + ahalf * 16);
            __syncthreads();

            // ---- ldmatrix + 32 MMAs on buffer 'buf' ----
            const uint32_t abase = smA + buf * A_BUF_BYTES;
            const uint32_t bbase = smB + buf * B_BUF_BYTES;
            uint32_t af[4][4], bf[4][4];
#pragma unroll
            for (int mt = 0; mt < 4; mt++)
                ldmx4(af[mt], abase + aoff + mt * 16 * APITCH);
#pragma unroll
            for (int ng = 0; ng < 4; ng++)
                ldmx4(bf[ng], bbase + boff + ng * 16 * BPITCH);
#pragma unroll
            for (int mt = 0; mt < 4; mt++)
#pragma unroll
                for (int ng = 0; ng < 4; ng++) {
                    mma16816(acc[mt][2 * ng],     af[mt], bf[ng][0], bf[ng][1]);
                    mma16816(acc[mt][2 * ng + 1], af[mt], bf[ng][2], bf[ng][3]);
                }
        }
    }

    // ---- epilogue ----
    const int ml = lid >> 2;
    const int nl = (lid & 3) * 2;
#pragma unroll
    for (int mt = 0; mt < 4; mt++) {
#pragma unroll
        for (int nt = 0; nt < 8; nt++) {
            int o = mh * 128 + wm * 64 + mt * 16 + ml;
            int n = wn * 64 + nt * 8 + nl;
            int h = h0 + (n >> 6);
            int wc = n & 63;
            float* op = out + (((size_t)b * OO + o) * HH + h) * WW + wc;
            *(float2*)op = make_float2(acc[mt][nt][0], acc[mt][nt][1]);
            float* op2 = op + (size_t)8 * HH * WW;    // o + 8
            *(float2*)op2 = make_float2(acc[mt][nt][2], acc[mt][nt][3]);
        }
    }
}

extern "C" void kernel_launch(void* const* d_in, const int* in_sizes, int n_in,
                              void* d_out, int out_size) {
    const float* x      = (const float*)d_in[0];   // [8,256,64,64]
    const float* offset = (const float*)d_in[1];   // [8,18,64,64]
    const float* weight = (const float*)d_in[2];   // [256,256,3,3]
    float* out = (float*)d_out;                    // [8,256,64,64]

    cudaFuncSetAttribute(dcn_kernel,
                         cudaFuncAttributeMaxDynamicSharedMemorySize, SMEM_TOTAL);

    int nprep = NCH * OO * 16;
    prep_w<<<(nprep + 255) / 256, 256>>>(weight);

    dim3 grid(HH / NROWS, BB, 2);    // (16 rowgroups, 8 batches, 2 o-halves)
    dcn_kernel<<<grid, 256, SMEM_TOTAL>>>(x, offset, out);
}

// round 7
// speedup vs baseline: 1.5280x; 1.5280x over previous
#include <cuda_runtime.h>
#include <cuda_fp16.h>
#include <cstdint>

#define BB 8
#define CC 256
#define HH 64
#define WW 64
#define OO 256
#define KK2 9
#define PLANE 4096
#define NROWS 4
#define NPIX 256          // N per CTA
#define NCH 144           // chunks: 16 c-groups (outer) x 9 taps (inner)
#define APITCH 48
#define BPITCH 48
#define A_BUF_BYTES (128 * APITCH)   // 6144
#define B_BUF_BYTES (256 * BPITCH)   // 12288

// smem layout (dynamic)
#define SM_TAPS 0                    // float2[9*256] = 18432
#define SM_A    18432                // 2 * 6144  -> 30720
#define SM_B    30720                // 2 * 12288 -> 55296
#define SMEM_TOTAL 55296

__device__ __forceinline__ uint32_t smem_u32(const void* p) {
    uint32_t a;
    asm("{ .reg .u64 t; cvta.to.shared.u64 t, %1; cvt.u32.u64 %0, t; }"
        : "=r"(a) : "l"(p));
    return a;
}

__device__ __forceinline__ void ldmx4(uint32_t* r, uint32_t addr) {
    asm volatile("ldmatrix.sync.aligned.m8n8.x4.shared.b16 {%0,%1,%2,%3}, [%4];"
                 : "=r"(r[0]), "=r"(r[1]), "=r"(r[2]), "=r"(r[3]) : "r"(addr));
}

__device__ __forceinline__ void mma16816(float* d, const uint32_t* a,
                                         uint32_t b0, uint32_t b1) {
    asm volatile(
        "mma.sync.aligned.m16n8k16.row.col.f32.f16.f16.f32 "
        "{%0,%1,%2,%3}, {%4,%5,%6,%7}, {%8,%9}, {%0,%1,%2,%3};"
        : "+f"(d[0]), "+f"(d[1]), "+f"(d[2]), "+f"(d[3])
        : "r"(a[0]), "r"(a[1]), "r"(a[2]), "r"(a[3]), "r"(b0), "r"(b1));
}

// Pre-packed fp16 weights, chunk-major: g_wh[q][o][j], q = cg*9 + k, j = c-local
__device__ __half g_wh[NCH * OO * 16];             // 1.18 MB
// NHWC-grouped fp16 input: g_xh[b][cg][y][x][16]  (16 channels contiguous, 32B)
__device__ __half g_xh[(size_t)BB * 16 * PLANE * 16];   // 16.8 MB

__global__ void prep_w(const float* __restrict__ w) {
    int n = blockIdx.x * blockDim.x + threadIdx.x;   // over 144*256*16
    if (n >= NCH * OO * 16) return;
    int j = n & 15;
    int o = (n >> 4) & 255;
    int q = n >> 12;
    int cg = q / 9;
    int k  = q - cg * 9;
    int c  = cg * 16 + j;
    g_wh[n] = __float2half(w[(o * CC + c) * KK2 + k]);
}

__global__ void prep_x(const float* __restrict__ x) {
    int n = blockIdx.x * blockDim.x + threadIdx.x;   // over 8*16*4096
    if (n >= BB * 16 * PLANE) return;
    int pix = n & 4095;
    int cg  = (n >> 12) & 15;
    int b   = n >> 16;
    const float* src = x + ((size_t)b * CC + cg * 16) * PLANE + pix;
    __half hbuf[16];
#pragma unroll
    for (int j = 0; j < 16; j++)
        hbuf[j] = __float2half(src[(size_t)j * PLANE]);
    uint4* dst = (uint4*)(g_xh + ((size_t)(b * 16 + cg) * PLANE + pix) * 16);
    dst[0] = *(uint4*)&hbuf[0];
    dst[1] = *(uint4*)&hbuf[8];
}

// Load bilinear tap: corner weights (OOB->0) + 8 x LDG.128 of 16ch fp16 corners
__device__ __forceinline__ void sample_load(const float2* taps, const char* xh_b,
                                            int k, int cg, int tid,
                                            uint4* cr, float* cw) {
    float2 t = taps[k * 256 + tid];
    float y0f = floorf(t.x), x0f = floorf(t.y);
    float fy = t.x - y0f, fx = t.y - x0f;
    int y0 = (int)y0f, x0 = (int)x0f;
    int y1 = y0 + 1,  x1 = x0 + 1;
    bool vy0 = (y0 >= 0) && (y0 < HH);
    bool vy1 = (y1 >= 0) && (y1 < HH);
    bool vx0 = (x0 >= 0) && (x0 < WW);
    bool vx1 = (x1 >= 0) && (x1 < WW);
    cw[0] = (vy0 && vx0) ? (1.f - fy) * (1.f - fx) : 0.f;
    cw[1] = (vy0 && vx1) ? (1.f - fy) * fx : 0.f;
    cw[2] = (vy1 && vx0) ? fy * (1.f - fx) : 0.f;
    cw[3] = (vy1 && vx1) ? fy * fx : 0.f;
    int cy0 = min(max(y0, 0), HH - 1), cy1 = min(max(y1, 0), HH - 1);
    int cx0 = min(max(x0, 0), WW - 1), cx1 = min(max(x1, 0), WW - 1);
    const char* pb = xh_b + (size_t)cg * (PLANE * 32);
    const char* a00 = pb + (cy0 * WW + cx0) * 32;
    const char* a01 = pb + (cy0 * WW + cx1) * 32;
    const char* a10 = pb + (cy1 * WW + cx0) * 32;
    const char* a11 = pb + (cy1 * WW + cx1) * 32;
    cr[0] = __ldg((const uint4*)a00);
    cr[1] = __ldg((const uint4*)a01);
    cr[2] = __ldg((const uint4*)a10);
    cr[3] = __ldg((const uint4*)a11);
    cr[4] = __ldg((const uint4*)(a00 + 16));
    cr[5] = __ldg((const uint4*)(a01 + 16));
    cr[6] = __ldg((const uint4*)(a10 + 16));
    cr[7] = __ldg((const uint4*)(a11 + 16));
}

__global__ __launch_bounds__(256, 1)
void dcn_kernel(const float* __restrict__ x,
                const float* __restrict__ offset,
                float* __restrict__ out) {
    extern __shared__ char smem[];
    float2* taps = (float2*)(smem + SM_TAPS);   // [k*256 + p] = (py, px)

    const int tid = threadIdx.x;
    const int lid = tid & 31;
    const int wid = tid >> 5;
    const int wm  = wid >> 2;            // 0..1 : warp m (64 rows)
    const int wn  = wid & 3;             // 0..3 : warp n (64 px)
    const int b   = blockIdx.y;
    const int h0  = blockIdx.x * NROWS;
    const int mh  = blockIdx.z;          // o-half (0/1)

    // ---- precompute absolute sample coords per (k, pixel) ----
    for (int i = tid; i < KK2 * NPIX; i += 256) {
        int k = i >> 8;
        int p = i & 255;
        int rl = p >> 6, wc = p & 63;
        int h = h0 + rl;
        int ky = k / 3, kx = k - ky * 3;
        float dy = offset[(((b * 2 * KK2 + 2 * k    ) * HH + h) * WW) + wc];
        float dx = offset[(((b * 2 * KK2 + 2 * k + 1) * HH + h) * WW) + wc];
        taps[i] = make_float2((float)(h - 1 + ky) + dy, (float)(wc - 1 + kx) + dx);
    }

    const uint32_t smA = smem_u32(smem + SM_A);
    const uint32_t smB = smem_u32(smem + SM_B);

    const int r   = lid & 7;
    const int sec = lid >> 3;
    const uint32_t aoff = (uint32_t)(wm * 64 + r + 8 * (sec & 1)) * APITCH
                        + (uint32_t)(sec >> 1) * 16;
    const uint32_t boff = (uint32_t)(wn * 64 + r + 8 * (sec >> 1)) * BPITCH
                        + (uint32_t)(sec & 1) * 16;

    const char* xh_b = (const char*)(g_xh + (size_t)b * 16 * PLANE * 16);
    const char* wsrc = (const char*)g_wh + (size_t)mh * 4096;  // m-half offset
    const int arow = tid >> 1, ahalf = tid & 1;

    float acc[4][8][4];
#pragma unroll
    for (int i = 0; i < 4; i++)
#pragma unroll
        for (int j = 0; j < 8; j++)
#pragma unroll
            for (int t = 0; t < 4; t++) acc[i][j][t] = 0.f;

    uint4  cr[8];     // corner data: [g*4 + corner], channels g*8..g*8+7
    float  cw[4];     // corner weights
    uint4  areg;
    __syncthreads();   // taps visible

    // ---- prologue: load taps + A for chunk 0 ----
    sample_load(taps, xh_b, 0, 0, tid, cr, cw);
    areg = *(const uint4*)(wsrc + arow * 32 + ahalf * 16);

    int k_nxt = 1, cg_nxt = 0;

    for (int q = 0; q < NCH; q++) {
        const int buf = q & 1;

        // ---- lerp prefetched corners -> 16 fp16 samples ----
        uint32_t sbuf[8];
#pragma unroll
        for (int g = 0; g < 2; g++) {
            const __half2* H00 = (const __half2*)&cr[g * 4 + 0];
            const __half2* H01 = (const __half2*)&cr[g * 4 + 1];
            const __half2* H10 = (const __half2*)&cr[g * 4 + 2];
            const __half2* H11 = (const __half2*)&cr[g * 4 + 3];
#pragma unroll
            for (int j = 0; j < 4; j++) {
                float2 f00 = __half22float2(H00[j]);
                float2 f01 = __half22float2(H01[j]);
                float2 f10 = __half22float2(H10[j]);
                float2 f11 = __half22float2(H11[j]);
                float s0 = cw[0] * f00.x + cw[1] * f01.x + cw[2] * f10.x + cw[3] * f11.x;
                float s1 = cw[0] * f00.y + cw[1] * f01.y + cw[2] * f10.y + cw[3] * f11.y;
                __half2 hh = __floats2half2_rn(s0, s1);
                sbuf[g * 4 + j] = *(uint32_t*)&hh;
            }
        }

        // ---- stage A + B into smem buffers ----
        {
            char* ad = smem + SM_A + buf * A_BUF_BYTES + arow * APITCH + ahalf * 16;
            *(uint4*)ad = areg;
            char* bd = smem + SM_B + buf * B_BUF_BYTES + tid * BPITCH;
            *(uint4*)(bd)      = *(uint4*)&sbuf[0];
            *(uint4*)(bd + 16) = *(uint4*)&sbuf[4];
        }
        __syncthreads();

        // ---- issue prefetch loads for q+1 (cover = MMA section below) ----
        if (q + 1 < NCH) {
            sample_load(taps, xh_b, k_nxt, cg_nxt, tid, cr, cw);
            areg = *(const uint4*)(wsrc + (size_t)(q + 1) * 8192
                                   + arow * 32 + ahalf * 16);
            if (++k_nxt == KK2) { k_nxt = 0; cg_nxt++; }
        }

        // ---- ldmatrix + 32 MMAs on buffer 'buf' ----
        const uint32_t abase = smA + buf * A_BUF_BYTES;
        const uint32_t bbase = smB + buf * B_BUF_BYTES;
        uint32_t af[4][4], bf[4][4];
#pragma unroll
        for (int mt = 0; mt < 4; mt++)
            ldmx4(af[mt], abase + aoff + mt * 16 * APITCH);
#pragma unroll
        for (int ng = 0; ng < 4; ng++)
            ldmx4(bf[ng], bbase + boff + ng * 16 * BPITCH);
#pragma unroll
        for (int mt = 0; mt < 4; mt++)
#pragma unroll
            for (int ng = 0; ng < 4; ng++) {
                mma16816(acc[mt][2 * ng],     af[mt], bf[ng][0], bf[ng][1]);
                mma16816(acc[mt][2 * ng + 1], af[mt], bf[ng][2], bf[ng][3]);
            }
    }

    // ---- epilogue ----
    const int ml = lid >> 2;
    const int nl = (lid & 3) * 2;
#pragma unroll
    for (int mt = 0; mt < 4; mt++) {
#pragma unroll
        for (int nt = 0; nt < 8; nt++) {
            int o = mh * 128 + wm * 64 + mt * 16 + ml;
            int n = wn * 64 + nt * 8 + nl;
            int h = h0 + (n >> 6);
            int wc = n & 63;
            float* op = out + (((size_t)b * OO + o) * HH + h) * WW + wc;
            *(float2*)op = make_float2(acc[mt][nt][0], acc[mt][nt][1]);
            float* op2 = op + (size_t)8 * HH * WW;    // o + 8
            *(float2*)op2 = make_float2(acc[mt][nt][2], acc[mt][nt][3]);
        }
    }
}

extern "C" void kernel_launch(void* const* d_in, const int* in_sizes, int n_in,
                              void* d_out, int out_size) {
    const float* x      = (const float*)d_in[0];   // [8,256,64,64]
    const float* offset = (const float*)d_in[1];   // [8,18,64,64]
    const float* weight = (const float*)d_in[2];   // [256,256,3,3]
    float* out = (float*)d_out;                    // [8,256,64,64]

    cudaFuncSetAttribute(dcn_kernel,
                         cudaFuncAttributeMaxDynamicSharedMemorySize, SMEM_TOTAL);

    int nprep = NCH * OO * 16;
    prep_w<<<(nprep + 255) / 256, 256>>>(weight);
    int nx = BB * 16 * PLANE;
    prep_x<<<(nx + 255) / 256, 256>>>(x);

    dim3 grid(HH / NROWS, BB, 2);    // (16 rowgroups, 8 batches, 2 o-halves)
    dcn_kernel<<<grid, 256, SMEM_TOTAL>>>(x, offset, out);
}

// round 8
// speedup vs baseline: 2.0031x; 1.3109x over previous
#include <cuda_runtime.h>
#include <cuda_fp16.h>
#include <cstdint>

#define BB 8
#define CC 256
#define HH 64
#define WW 64
#define OO 256
#define KK2 9
#define PLANE 4096
#define NROWS 2
#define NPIX 128          // N per CTA
#define NCH 144           // chunks: 16 c-groups (outer) x 9 taps (inner)
#define APITCH 48
#define BPITCH 48
#define A_BUF_BYTES (128 * APITCH)   // 6144
#define B_BUF_BYTES (128 * BPITCH)   // 6144

// smem layout (dynamic)
#define SM_TAPS 0                    // float2[9*128] = 9216
#define SM_A    9216                 // 2 * 6144  -> 21504
#define SM_B    21504                // 2 * 6144  -> 33792
#define SMEM_TOTAL 33792

__device__ __forceinline__ uint32_t smem_u32(const void* p) {
    uint32_t a;
    asm("{ .reg .u64 t; cvta.to.shared.u64 t, %1; cvt.u32.u64 %0, t; }"
        : "=r"(a) : "l"(p));
    return a;
}

__device__ __forceinline__ void ldmx4(uint32_t* r, uint32_t addr) {
    asm volatile("ldmatrix.sync.aligned.m8n8.x4.shared.b16 {%0,%1,%2,%3}, [%4];"
                 : "=r"(r[0]), "=r"(r[1]), "=r"(r[2]), "=r"(r[3]) : "r"(addr));
}

__device__ __forceinline__ void mma16816(float* d, const uint32_t* a,
                                         uint32_t b0, uint32_t b1) {
    asm volatile(
        "mma.sync.aligned.m16n8k16.row.col.f32.f16.f16.f32 "
        "{%0,%1,%2,%3}, {%4,%5,%6,%7}, {%8,%9}, {%0,%1,%2,%3};"
        : "+f"(d[0]), "+f"(d[1]), "+f"(d[2]), "+f"(d[3])
        : "r"(a[0]), "r"(a[1]), "r"(a[2]), "r"(a[3]), "r"(b0), "r"(b1));
}

// Pre-packed fp16 weights, chunk-major: g_wh[q][o][j], q = cg*9 + k, j = c-local
__device__ __half g_wh[NCH * OO * 16];             // 1.18 MB
// NHWC-grouped fp16 input: g_xh[b][cg][y][x][16]  (16 channels contiguous, 32B)
__device__ __half g_xh[(size_t)BB * 16 * PLANE * 16];   // 16.8 MB

__global__ void prep_w(const float* __restrict__ w) {
    int n = blockIdx.x * blockDim.x + threadIdx.x;   // over 144*256*16
    if (n >= NCH * OO * 16) return;
    int j = n & 15;
    int o = (n >> 4) & 255;
    int q = n >> 12;
    int cg = q / 9;
    int k  = q - cg * 9;
    int c  = cg * 16 + j;
    g_wh[n] = __float2half(w[(o * CC + c) * KK2 + k]);
}

__global__ void prep_x(const float* __restrict__ x) {
    int n = blockIdx.x * blockDim.x + threadIdx.x;   // over 8*16*4096
    if (n >= BB * 16 * PLANE) return;
    int pix = n & 4095;
    int cg  = (n >> 12) & 15;
    int b   = n >> 16;
    const float* src = x + ((size_t)b * CC + cg * 16) * PLANE + pix;
    __half hbuf[16];
#pragma unroll
    for (int j = 0; j < 16; j++)
        hbuf[j] = __float2half(src[(size_t)j * PLANE]);
    uint4* dst = (uint4*)(g_xh + ((size_t)(b * 16 + cg) * PLANE + pix) * 16);
    dst[0] = *(uint4*)&hbuf[0];
    dst[1] = *(uint4*)&hbuf[8];
}

// Tap load for one pixel / one 8-channel group: weights (OOB->0) + 4 LDG.128
__device__ __forceinline__ void sample_load(const float2* taps, const char* xh_b,
                                            int k, int cg, int px, int g,
                                            uint4* cr, float* cw) {
    float2 t = taps[k * NPIX + px];
    float y0f = floorf(t.x), x0f = floorf(t.y);
    float fy = t.x - y0f, fx = t.y - x0f;
    int y0 = (int)y0f, x0 = (int)x0f;
    int y1 = y0 + 1,  x1 = x0 + 1;
    bool vy0 = (y0 >= 0) && (y0 < HH);
    bool vy1 = (y1 >= 0) && (y1 < HH);
    bool vx0 = (x0 >= 0) && (x0 < WW);
    bool vx1 = (x1 >= 0) && (x1 < WW);
    cw[0] = (vy0 && vx0) ? (1.f - fy) * (1.f - fx) : 0.f;
    cw[1] = (vy0 && vx1) ? (1.f - fy) * fx : 0.f;
    cw[2] = (vy1 && vx0) ? fy * (1.f - fx) : 0.f;
    cw[3] = (vy1 && vx1) ? fy * fx : 0.f;
    int cy0 = min(max(y0, 0), HH - 1), cy1 = min(max(y1, 0), HH - 1);
    int cx0 = min(max(x0, 0), WW - 1), cx1 = min(max(x1, 0), WW - 1);
    const char* pb = xh_b + (size_t)cg * (PLANE * 32) + g * 16;
    cr[0] = __ldg((const uint4*)(pb + (cy0 * WW + cx0) * 32));
    cr[1] = __ldg((const uint4*)(pb + (cy0 * WW + cx1) * 32));
    cr[2] = __ldg((const uint4*)(pb + (cy1 * WW + cx0) * 32));
    cr[3] = __ldg((const uint4*)(pb + (cy1 * WW + cx1) * 32));
}

__global__ __launch_bounds__(256, 2)
void dcn_kernel(const float* __restrict__ x,
                const float* __restrict__ offset,
                float* __restrict__ out) {
    extern __shared__ char smem[];
    float2* taps = (float2*)(smem + SM_TAPS);   // [k*128 + p] = (py, px)

    const int tid = threadIdx.x;
    const int lid = tid & 31;
    const int wid = tid >> 5;
    const int wm  = wid >> 2;            // 0..1 : warp m (64 rows)
    const int wn  = wid & 3;             // 0..3 : warp n (32 px)
    const int b   = blockIdx.y;
    const int h0  = blockIdx.x * NROWS;
    const int mh  = blockIdx.z;          // o-half (0/1)

    // ---- precompute absolute sample coords per (k, pixel) ----
    for (int i = tid; i < KK2 * NPIX; i += 256) {
        int k = i >> 7;
        int p = i & 127;
        int rl = p >> 6, wc = p & 63;
        int h = h0 + rl;
        int ky = k / 3, kx = k - ky * 3;
        float dy = offset[(((b * 2 * KK2 + 2 * k    ) * HH + h) * WW) + wc];
        float dx = offset[(((b * 2 * KK2 + 2 * k + 1) * HH + h) * WW) + wc];
        taps[i] = make_float2((float)(h - 1 + ky) + dy, (float)(wc - 1 + kx) + dx);
    }

    const uint32_t smA = smem_u32(smem + SM_A);
    const uint32_t smB = smem_u32(smem + SM_B);

    const int r   = lid & 7;
    const int sec = lid >> 3;
    const uint32_t aoff = (uint32_t)(wm * 64 + r + 8 * (sec & 1)) * APITCH
                        + (uint32_t)(sec >> 1) * 16;
    const uint32_t boff = (uint32_t)(wn * 32 + r + 8 * (sec >> 1)) * BPITCH
                        + (uint32_t)(sec & 1) * 16;

    const char* xh_b = (const char*)(g_xh + (size_t)b * 16 * PLANE * 16);
    const char* wsrc = (const char*)g_wh + (size_t)mh * 4096;  // m-half offset
    const int arow = tid >> 1, ahalf = tid & 1;
    const int px_my = tid >> 1, g_my = tid & 1;    // B-sampling assignment

    float acc[4][4][4];
#pragma unroll
    for (int i = 0; i < 4; i++)
#pragma unroll
        for (int j = 0; j < 4; j++)
#pragma unroll
            for (int t = 0; t < 4; t++) acc[i][j][t] = 0.f;

    uint4  cr[4];     // 4 corners, 8 channels each
    float  cw[4];
    uint4  areg;
    __syncthreads();   // taps visible

    // ---- prologue: chunk 0 loads ----
    sample_load(taps, xh_b, 0, 0, px_my, g_my, cr, cw);
    areg = *(const uint4*)(wsrc + arow * 32 + ahalf * 16);

    int k_nxt = 1, cg_nxt = 0;

    for (int q = 0; q < NCH; q++) {
        const int buf = q & 1;

        // ---- lerp prefetched corners -> 8 fp16 samples ----
        uint32_t sbuf[4];
        {
            const __half2* H00 = (const __half2*)&cr[0];
            const __half2* H01 = (const __half2*)&cr[1];
            const __half2* H10 = (const __half2*)&cr[2];
            const __half2* H11 = (const __half2*)&cr[3];
#pragma unroll
            for (int j = 0; j < 4; j++) {
                float2 f00 = __half22float2(H00[j]);
                float2 f01 = __half22float2(H01[j]);
                float2 f10 = __half22float2(H10[j]);
                float2 f11 = __half22float2(H11[j]);
                float s0 = cw[0] * f00.x + cw[1] * f01.x + cw[2] * f10.x + cw[3] * f11.x;
                float s1 = cw[0] * f00.y + cw[1] * f01.y + cw[2] * f10.y + cw[3] * f11.y;
                __half2 hh = __floats2half2_rn(s0, s1);
                sbuf[j] = *(uint32_t*)&hh;
            }
        }

        // ---- stage A + B into smem buffers ----
        {
            char* ad = smem + SM_A + buf * A_BUF_BYTES + arow * APITCH + ahalf * 16;
            *(uint4*)ad = areg;
            char* bd = smem + SM_B + buf * B_BUF_BYTES + px_my * BPITCH + g_my * 16;
            *(uint4*)bd = *(uint4*)&sbuf[0];
        }
        __syncthreads();

        // ---- issue prefetch loads for q+1 (cover = MMA section below) ----
        if (q + 1 < NCH) {
            sample_load(taps, xh_b, k_nxt, cg_nxt, px_my, g_my, cr, cw);
            areg = *(const uint4*)(wsrc + (size_t)(q + 1) * 8192
                                   + arow * 32 + ahalf * 16);
            if (++k_nxt == KK2) { k_nxt = 0; cg_nxt++; }
        }

        // ---- ldmatrix + 16 MMAs on buffer 'buf' ----
        const uint32_t abase = smA + buf * A_BUF_BYTES;
        const uint32_t bbase = smB + buf * B_BUF_BYTES;
        uint32_t af[4][4], bf[2][4];
#pragma unroll
        for (int mt = 0; mt < 4; mt++)
            ldmx4(af[mt], abase + aoff + mt * 16 * APITCH);
#pragma unroll
        for (int ng = 0; ng < 2; ng++)
            ldmx4(bf[ng], bbase + boff + ng * 16 * BPITCH);
#pragma unroll
        for (int mt = 0; mt < 4; mt++)
#pragma unroll
            for (int ng = 0; ng < 2; ng++) {
                mma16816(acc[mt][2 * ng],     af[mt], bf[ng][0], bf[ng][1]);
                mma16816(acc[mt][2 * ng + 1], af[mt], bf[ng][2], bf[ng][3]);
            }
    }

    // ---- epilogue ----
    const int ml = lid >> 2;
    const int nl = (lid & 3) * 2;
#pragma unroll
    for (int mt = 0; mt < 4; mt++) {
#pragma unroll
        for (int nt = 0; nt < 4; nt++) {
            int o = mh * 128 + wm * 64 + mt * 16 + ml;
            int n = wn * 32 + nt * 8 + nl;
            int h = h0 + (n >> 6);
            int wc = n & 63;
            float* op = out + (((size_t)b * OO + o) * HH + h) * WW + wc;
            *(float2*)op = make_float2(acc[mt][nt][0], acc[mt][nt][1]);
            float* op2 = op + (size_t)8 * HH * WW;    // o + 8
            *(float2*)op2 = make_float2(acc[mt][nt][2], acc[mt][nt][3]);
        }
    }
}

extern "C" void kernel_launch(void* const* d_in, const int* in_sizes, int n_in,
                              void* d_out, int out_size) {
    const float* x      = (const float*)d_in[0];   // [8,256,64,64]
    const float* offset = (const float*)d_in[1];   // [8,18,64,64]
    const float* weight = (const float*)d_in[2];   // [256,256,3,3]
    float* out = (float*)d_out;                    // [8,256,64,64]

    cudaFuncSetAttribute(dcn_kernel,
                         cudaFuncAttributeMaxDynamicSharedMemorySize, SMEM_TOTAL);

    int nprep = NCH * OO * 16;
    prep_w<<<(nprep + 255) / 256, 256>>>(weight);
    int nx = BB * 16 * PLANE;
    prep_x<<<(nx + 255) / 256, 256>>>(x);

    dim3 grid(HH / NROWS, BB, 2);    // (32 rowgroups, 8 batches, 2 o-halves)
    dcn_kernel<<<grid, 256, SMEM_TOTAL>>>(x, offset, out);
}